// round 13
// baseline (speedup 1.0000x reference)
#include <cuda_runtime.h>
#include <cuda_fp16.h>
#include <cstdint>

#define HWs 4096
#define Cc  256
#define NB  2

// ---------------- scratch (fp16) ------------------------------------------------
__device__ __align__(256) __half g_xt[4][HWs][Cc];
__device__ __align__(256) __half g_q[NB][HWs][128];
__device__ __align__(256) __half g_k[NB][2][HWs][128];
__device__ __align__(256) __half g_v[NB][2][Cc][HWs];
__device__ __align__(256) __half g_P[4][HWs][HWs];      // unnormalized exp(S)
__device__ __align__(256) float g_rowsum[4][HWs];

// ---------------- helpers --------------------------------------------------------
__device__ __forceinline__ uint32_t smem_u32(const void* p) {
    uint32_t a;
    asm("{ .reg .u64 t; cvta.to.shared.u64 t, %1; cvt.u32.u64 %0, t; }"
        : "=r"(a) : "l"(p));
    return a;
}
__device__ __forceinline__ void ldmatrix_x4(uint32_t* r, uint32_t addr) {
    asm volatile("ldmatrix.sync.aligned.m8n8.x4.shared.b16 {%0,%1,%2,%3}, [%4];"
        : "=r"(r[0]), "=r"(r[1]), "=r"(r[2]), "=r"(r[3]) : "r"(addr));
}
__device__ __forceinline__ void mma_f32(float* d, const uint32_t* a,
                                        uint32_t b0, uint32_t b1) {
    asm volatile(
        "mma.sync.aligned.m16n8k16.row.col.f32.f16.f16.f32 "
        "{%0,%1,%2,%3}, {%4,%5,%6,%7}, {%8,%9}, {%0,%1,%2,%3};"
        : "+f"(d[0]), "+f"(d[1]), "+f"(d[2]), "+f"(d[3])
        : "r"(a[0]), "r"(a[1]), "r"(a[2]), "r"(a[3]), "r"(b0), "r"(b1));
}
__device__ __forceinline__ void mma_f16(uint32_t* d, const uint32_t* a,
                                        uint32_t b0, uint32_t b1) {
    asm volatile(
        "mma.sync.aligned.m16n8k16.row.col.f16.f16.f16.f16 "
        "{%0,%1}, {%2,%3,%4,%5}, {%6,%7}, {%0,%1};"
        : "+r"(d[0]), "+r"(d[1])
        : "r"(a[0]), "r"(a[1]), "r"(a[2]), "r"(a[3]), "r"(b0), "r"(b1));
}
#define CP_ASYNC16(dst, src) \
    asm volatile("cp.async.cg.shared.global [%0], [%1], 16;" :: "r"(dst), "l"(src))

#define MBARRIER_INIT(mb, c) \
    asm volatile("mbarrier.init.shared.b64 [%0], %1;" :: "r"((uint32_t)(mb)), "r"((uint32_t)(c)) : "memory")
#define MBAR_ARRIVE(mb) \
    asm volatile("mbarrier.arrive.shared.b64 _, [%0];" :: "r"((uint32_t)(mb)) : "memory")
// NOTE: .noinc is load-bearing — default variant nets to zero and deadlocks.
#define CP_ASYNC_MBAR_ARRIVE_NOINC(mb) \
    asm volatile("cp.async.mbarrier.arrive.noinc.shared.b64 [%0];" :: "r"((uint32_t)(mb)) : "memory")

#define MBARRIER_WAIT_PARITY(mb, ph) do { \
    uint32_t _mb = (uint32_t)(mb); uint32_t _p = (uint32_t)(ph); uint32_t _done; \
    asm volatile("{\n\t.reg .pred p;\n\t" \
        "mbarrier.try_wait.parity.acquire.cta.shared::cta.b64 p, [%1], %2;\n\t" \
        "selp.b32 %0, 1, 0, p;\n\t}" : "=r"(_done) : "r"(_mb), "r"(_p) : "memory"); \
    if (!_done) { \
        asm volatile("{\n\t.reg .pred P1;\n\t" \
            "WAIT_LOOP_%=:\n\t" \
            "mbarrier.try_wait.parity.acquire.cta.shared::cta.b64 P1, [%0], %1, 0x989680;\n\t" \
            "@P1 bra.uni WAIT_DONE_%=;\n\t" \
            "bra.uni WAIT_LOOP_%=;\n\t" \
            "WAIT_DONE_%=:\n\t}" :: "r"(_mb), "r"(_p) : "memory"); \
    } \
} while (0)

__device__ __forceinline__ uint32_t pack_h2(float a, float b) {
    __half2 h = __floats2half2_rn(a, b);
    return *reinterpret_cast<uint32_t*>(&h);
}
__device__ __forceinline__ float2 unpack_h2(uint32_t w) {
    return __half22float2(*reinterpret_cast<__half2*>(&w));
}

// ---------------------------------------------------------------------------
// Stage 0: transpose+convert x -> g_xt[t][n][c] fp16.  grid (128, 8, 4)
// ---------------------------------------------------------------------------
__global__ __launch_bounds__(256) void xt_kernel(
    const float* __restrict__ x1, const float* __restrict__ x2)
{
    const int t = blockIdx.z;
    const int br = t >> 1, b = t & 1;
    const float* src = (br ? x2 : x1) + (size_t)b * Cc * HWs;

    const int n0 = blockIdx.x * 32;
    const int c0 = blockIdx.y * 32;

    __shared__ float tile[32][33];
    const int tx = threadIdx.x & 31;
    const int ty = threadIdx.x >> 5;

    #pragma unroll
    for (int j = 0; j < 4; j++) {
        const int cl = ty * 4 + j;
        tile[cl][tx] = src[(size_t)(c0 + cl) * HWs + n0 + tx];
    }
    __syncthreads();
    #pragma unroll
    for (int j = 0; j < 4; j++) {
        const int nl = ty * 4 + j;
        g_xt[t][n0 + nl][c0 + tx] = __float2half(tile[tx][nl]);
    }
}

// ---------------------------------------------------------------------------
// Stage A: projections via fp16 mma (f16 accum).  (unchanged)
// ---------------------------------------------------------------------------
#define PAP 264

__global__ __launch_bounds__(256) void proj_mma(
    const float* __restrict__ Wq1, const float* __restrict__ bq1,
    const float* __restrict__ Wk1, const float* __restrict__ bk1,
    const float* __restrict__ Wv1, const float* __restrict__ bv1,
    const float* __restrict__ Wq2, const float* __restrict__ bq2,
    const float* __restrict__ Wk2, const float* __restrict__ bk2,
    const float* __restrict__ Wv2, const float* __restrict__ bv2)
{
    extern __shared__ __half smP[];
    __half* As = smP;
    __half* Bs = smP + 64 * PAP;

    const int combo = blockIdx.z;
    const int b  = combo >> 1;
    const int br = combo & 1;
    const int t  = br * 2 + b;

    const float* Wq = br ? Wq2 : Wq1;
    const float* Wk = br ? Wk2 : Wk1;
    const float* Wv = br ? Wv2 : Wv1;
    const float* bq = br ? bq2 : bq1;
    const float* bk = br ? bk2 : bk1;
    const float* bv = br ? bv2 : bv1;

    const int m0 = blockIdx.y * 64;
    const int n0 = blockIdx.x * 128;

    const int cls = (blockIdx.y == 0) ? 0 : (blockIdx.y < 3 ? 1 : 2);
    const float* Wbase = (cls == 0) ? Wq : (cls == 1 ? Wk : Wv);
    const int    roff  = (cls == 0) ? 0  : (cls == 1 ? 64 : 192);

    const int tid = threadIdx.x;

    #pragma unroll
    for (int s = 0; s < 16; s++) {
        const int i = tid + s * 256;
        const int r = i >> 6;
        const int c = (i & 63) * 4;
        float4 w4 = *reinterpret_cast<const float4*>(
            Wbase + (size_t)(m0 - roff + r) * Cc + c);
        uint2 v;
        v.x = pack_h2(w4.x, w4.y);
        v.y = pack_h2(w4.z, w4.w);
        *reinterpret_cast<uint2*>(&As[r * PAP + c]) = v;
    }
    #pragma unroll
    for (int s = 0; s < 16; s++) {
        const int i = tid + s * 256;
        const int r = i >> 5;
        const int c = (i & 31) * 8;
        uint4 v = *reinterpret_cast<const uint4*>(&g_xt[t][n0 + r][c]);
        *reinterpret_cast<uint4*>(&Bs[r * PAP + c]) = v;
    }
    __syncthreads();

    const int w = tid >> 5, l = tid & 31;
    const int wm = w >> 2, wn = w & 3;
    const int lrow = l & 15, lcol = (l >> 4) * 8;
    const uint32_t a_base = smem_u32(As + (wm * 32) * PAP);
    const uint32_t b_base = smem_u32(Bs + (wn * 32) * PAP);

    uint32_t acc[2][4][2];
    #pragma unroll
    for (int i = 0; i < 2; i++)
        #pragma unroll
        for (int j = 0; j < 4; j++) { acc[i][j][0] = 0u; acc[i][j][1] = 0u; }

    #pragma unroll
    for (int k = 0; k < 256; k += 16) {
        uint32_t af[2][4], bf[2][4];
        #pragma unroll
        for (int mi = 0; mi < 2; mi++)
            ldmatrix_x4(af[mi], a_base + ((mi * 16 + lrow) * PAP + k + lcol) * 2);
        #pragma unroll
        for (int nj = 0; nj < 2; nj++)
            ldmatrix_x4(bf[nj], b_base + ((nj * 16 + lrow) * PAP + k + lcol) * 2);
        #pragma unroll
        for (int mi = 0; mi < 2; mi++)
            #pragma unroll
            for (int ni = 0; ni < 4; ni++)
                mma_f16(acc[mi][ni], af[mi], bf[ni >> 1][ni & 1], bf[ni >> 1][(ni & 1) + 2]);
    }

    #pragma unroll
    for (int mi = 0; mi < 2; mi++) {
        const int r0 = wm * 32 + mi * 16 + (l >> 2);
        #pragma unroll
        for (int ni = 0; ni < 4; ni++) {
            const int n = n0 + wn * 32 + ni * 8 + (l & 3) * 2;
            float2 dlo = unpack_h2(acc[mi][ni][0]);
            float2 dhi = unpack_h2(acc[mi][ni][1]);
            if (cls == 0) {
                const int r = m0 + r0, r8 = r + 8;
                g_q[b][n][2 * r + br]      = __float2half(dlo.x + bq[r]);
                g_q[b][n + 1][2 * r + br]  = __float2half(dlo.y + bq[r]);
                g_q[b][n][2 * r8 + br]     = __float2half(dhi.x + bq[r8]);
                g_q[b][n + 1][2 * r8 + br] = __float2half(dhi.y + bq[r8]);
            } else if (cls == 1) {
                const int c = m0 - 64 + r0, c8 = c + 8;
                g_k[b][br][n][c]      = __float2half(dlo.x + bk[c]);
                g_k[b][br][n + 1][c]  = __float2half(dlo.y + bk[c]);
                g_k[b][br][n][c8]     = __float2half(dhi.x + bk[c8]);
                g_k[b][br][n + 1][c8] = __float2half(dhi.y + bk[c8]);
            } else {
                const int c = m0 - 192 + r0, c8 = c + 8;
                *reinterpret_cast<uint32_t*>(&g_v[b][br][c][n])  = pack_h2(dlo.x + bv[c],  dlo.y + bv[c]);
                *reinterpret_cast<uint32_t*>(&g_v[b][br][c8][n]) = pack_h2(dhi.x + bv[c8], dhi.y + bv[c8]);
            }
        }
    }
}

// ---------------------------------------------------------------------------
// Stage B: logits (f16 accum) -> exp(S) fp16 + row sums.  (unchanged)
// ---------------------------------------------------------------------------
#define LP 136

__global__ __launch_bounds__(256) void logits_mma()
{
    extern __shared__ __half smL[];
    __half* As = smL;
    __half* Bs = smL + 128 * LP;

    const int combo = blockIdx.z;
    const int b = combo >> 1, br = combo & 1;
    const int n0 = blockIdx.y * 128;
    const int m0 = blockIdx.x * 128;
    const int tid = threadIdx.x;

    for (int i = tid; i < 2048; i += 256) {
        const int r = i >> 4, c = i & 15;
        uint4 v = reinterpret_cast<const uint4*>(&g_q[b][n0 + r][0])[c];
        *reinterpret_cast<uint4*>(&As[r * LP + c * 8]) = v;
        uint4 w = reinterpret_cast<const uint4*>(&g_k[b][br][m0 + r][0])[c];
        *reinterpret_cast<uint4*>(&Bs[r * LP + c * 8]) = w;
    }
    __syncthreads();

    const int w = tid >> 5, l = tid & 31;
    const int wn = w >> 2, wm = w & 3;
    const uint32_t a_base = smem_u32(As + (wn * 64) * LP);
    const uint32_t b_base = smem_u32(Bs + (wm * 32) * LP);
    const int lrow = l & 15, lcol = (l >> 4) * 8;

    uint32_t acc[4][4][2];
    #pragma unroll
    for (int i = 0; i < 4; i++)
        #pragma unroll
        for (int j = 0; j < 4; j++) { acc[i][j][0] = 0u; acc[i][j][1] = 0u; }

    #pragma unroll
    for (int k = 0; k < 128; k += 16) {
        uint32_t af[4][4], bf[2][4];
        #pragma unroll
        for (int mi = 0; mi < 4; mi++)
            ldmatrix_x4(af[mi], a_base + ((mi * 16 + lrow) * LP + k + lcol) * 2);
        #pragma unroll
        for (int nj = 0; nj < 2; nj++)
            ldmatrix_x4(bf[nj], b_base + ((nj * 16 + lrow) * LP + k + lcol) * 2);
        #pragma unroll
        for (int mi = 0; mi < 4; mi++)
            #pragma unroll
            for (int ni = 0; ni < 4; ni++)
                mma_f16(acc[mi][ni], af[mi], bf[ni >> 1][ni & 1], bf[ni >> 1][(ni & 1) + 2]);
    }

    __syncthreads();
    __half* St = As;
    const int nbl = wn * 64 + (l >> 2);
    const int mbl = wm * 32 + (l & 3) * 2;
    #pragma unroll
    for (int mi = 0; mi < 4; mi++) {
        #pragma unroll
        for (int ni = 0; ni < 4; ni++) {
            float2 dlo = unpack_h2(acc[mi][ni][0]);
            float2 dhi = unpack_h2(acc[mi][ni][1]);
            *reinterpret_cast<uint32_t*>(&St[(nbl + mi * 16) * LP + mbl + ni * 8]) =
                pack_h2(__expf(dlo.x), __expf(dlo.y));
            *reinterpret_cast<uint32_t*>(&St[(nbl + mi * 16 + 8) * LP + mbl + ni * 8]) =
                pack_h2(__expf(dhi.x), __expf(dhi.y));
        }
    }
    __syncthreads();

    #pragma unroll
    for (int s = 0; s < 8; s++) {
        const int i = tid + s * 256;
        const int r = i >> 4, c = (i & 15) * 8;
        uint4 v = *reinterpret_cast<const uint4*>(&St[r * LP + c]);
        *reinterpret_cast<uint4*>(&g_P[combo][n0 + r][m0 + c]) = v;
    }

    {
        const int r = tid >> 1;
        const int half = tid & 1;
        const uint32_t* row = reinterpret_cast<const uint32_t*>(&St[r * LP + half * 64]);
        float s = 0.0f;
        #pragma unroll
        for (int j = 0; j < 32; j++) {
            float2 p = unpack_h2(row[j]);
            s += p.x + p.y;
        }
        s += __shfl_xor_sync(0xffffffffu, s, 1);
        if (half == 0) atomicAdd(&g_rowsum[combo][n0 + r], s);
    }
}

// ---------------------------------------------------------------------------
// Stage D: out = (gamma/rowsum[n]) * (expS @ V^T) + x.
// Block tile 128c x 128n, K-chunk 64, 3-stage mbarrier ring (108KB smem)
// -> 2 CTAs/SM for cross-CTA tensor-pipe overlap.  8 warps (2c x 4n),
// warp tile 64c x 32n, f32 accum.  grid (32 n, 2 c, 4 combos) = 256 = 1 wave.
// ---------------------------------------------------------------------------
#define OPITCH 72
#define AH     (128 * OPITCH)           // halves in V part of a stage
#define STAGE  (256 * OPITCH)           // halves per stage (V + P)
#define NKT    64                       // 4096 / 64

__global__ __launch_bounds__(256, 2) void out_mma(
    const float* __restrict__ x1, const float* __restrict__ x2,
    const float* __restrict__ gamma, float* __restrict__ out)
{
    extern __shared__ __half smO[];     // [3][STAGE]
    __shared__ __align__(8) uint64_t s_full[3];
    __shared__ __align__(8) uint64_t s_empty[3];

    const int combo = blockIdx.z;
    const int b = combo >> 1, br = combo & 1;
    const int n0 = blockIdx.x * 128;
    const int c0 = blockIdx.y * 128;
    const int tid = threadIdx.x;

    if (tid == 0) {
        #pragma unroll
        for (int s = 0; s < 3; s++) {
            MBARRIER_INIT(smem_u32(&s_full[s]), 256);
            MBARRIER_INIT(smem_u32(&s_empty[s]), 256);
        }
    }
    __syncthreads();

    const __half* Vb = &g_v[b][br][c0][0];
    const __half* Pb = &g_P[combo][n0][0];

    // producer: fill stage (p % 3) with K-chunk p.  Empty-wait only on reuse.
    auto produce = [&](int p) {
        const int st = p % 3;
        if (p >= 3) {
            MBARRIER_WAIT_PARITY(smem_u32(&s_empty[st]), ((p / 3) - 1) & 1);
        }
        __half* base = smO + st * STAGE;
        const int k0 = p * 64;
        #pragma unroll
        for (int s = 0; s < 4; s++) {               // V: 128 rows x 8 chunks = 1024 uint4
            const int i = tid + s * 256;
            const int r = i >> 3, c = (i & 7) * 8;
            CP_ASYNC16(smem_u32(base + r * OPITCH + c),
                       Vb + (size_t)r * HWs + k0 + c);
        }
        #pragma unroll
        for (int s = 0; s < 4; s++) {               // P: 1024 uint4
            const int i = tid + s * 256;
            const int r = i >> 3, c = (i & 7) * 8;
            CP_ASYNC16(smem_u32(base + AH + r * OPITCH + c),
                       Pb + (size_t)r * HWs + k0 + c);
        }
        CP_ASYNC_MBAR_ARRIVE_NOINC(smem_u32(&s_full[st]));
    };

    const int w = tid >> 5, l = tid & 31;
    const int wc = w >> 2, wn = w & 3;          // 2c x 4n warp grid
    const int lrow = l & 15, lcol = (l >> 4) * 8;

    float acc[4][4][4];                          // 64c x 32n per warp
    #pragma unroll
    for (int i = 0; i < 4; i++)
        #pragma unroll
        for (int j = 0; j < 4; j++)
            #pragma unroll
            for (int q = 0; q < 4; q++) acc[i][j][q] = 0.0f;

    produce(0);
    produce(1);

    for (int kt = 0; kt < NKT; kt++) {
        const int st = kt % 3;
        MBARRIER_WAIT_PARITY(smem_u32(&s_full[st]), (kt / 3) & 1);
        if (kt + 2 < NKT) produce(kt + 2);

        const __half* base = smO + st * STAGE;
        const uint32_t a_base = smem_u32(base + (wc * 64) * OPITCH);
        const uint32_t b_base = smem_u32(base + AH + (wn * 32) * OPITCH);

        #pragma unroll
        for (int k = 0; k < 64; k += 16) {
            uint32_t af[4][4], bf[2][4];
            #pragma unroll
            for (int mi = 0; mi < 4; mi++)
                ldmatrix_x4(af[mi], a_base + ((mi * 16 + lrow) * OPITCH + k + lcol) * 2);
            #pragma unroll
            for (int nj = 0; nj < 2; nj++)
                ldmatrix_x4(bf[nj], b_base + ((nj * 16 + lrow) * OPITCH + k + lcol) * 2);
            #pragma unroll
            for (int mi = 0; mi < 4; mi++)
                #pragma unroll
                for (int ni = 0; ni < 4; ni++)
                    mma_f32(acc[mi][ni], af[mi], bf[ni >> 1][ni & 1], bf[ni >> 1][(ni & 1) + 2]);
        }
        MBAR_ARRIVE(smem_u32(&s_empty[st]));
    }

    const float g = gamma[0];
    const float* x = (br ? x2 : x1) + (size_t)b * Cc * HWs;
    float* ob = out + (size_t)(br * 2 + b) * Cc * HWs;

    const int cb = c0 + wc * 64 + (l >> 2);
    const int nb = n0 + wn * 32 + (l & 3) * 2;
    #pragma unroll
    for (int ni = 0; ni < 4; ni++) {
        const int n = nb + ni * 8;
        float2 rs = *reinterpret_cast<const float2*>(&g_rowsum[combo][n]);
        const float s0 = __fdividef(g, rs.x);
        const float s1 = __fdividef(g, rs.y);
        #pragma unroll
        for (int mi = 0; mi < 4; mi++) {
            const int c = cb + mi * 16;
            {
                float2 xi = *reinterpret_cast<const float2*>(x + (size_t)c * HWs + n);
                float2 o;
                o.x = fmaf(s0, acc[mi][ni][0], xi.x);
                o.y = fmaf(s1, acc[mi][ni][1], xi.y);
                *reinterpret_cast<float2*>(ob + (size_t)c * HWs + n) = o;
            }
            {
                float2 xi = *reinterpret_cast<const float2*>(x + (size_t)(c + 8) * HWs + n);
                float2 o;
                o.x = fmaf(s0, acc[mi][ni][2], xi.x);
                o.y = fmaf(s1, acc[mi][ni][3], xi.y);
                *reinterpret_cast<float2*>(ob + (size_t)(c + 8) * HWs + n) = o;
            }
        }
    }
}

// ---------------------------------------------------------------------------
extern "C" void kernel_launch(void* const* d_in, const int* in_sizes, int n_in,
                              void* d_out, int out_size)
{
    const float* input1 = (const float*)d_in[0];
    const float* input2 = (const float*)d_in[1];
    const float* Wq1 = (const float*)d_in[2];
    const float* bq1 = (const float*)d_in[3];
    const float* Wk1 = (const float*)d_in[4];
    const float* bk1 = (const float*)d_in[5];
    const float* Wv1 = (const float*)d_in[6];
    const float* bv1 = (const float*)d_in[7];
    const float* Wq2 = (const float*)d_in[8];
    const float* bq2 = (const float*)d_in[9];
    const float* Wk2 = (const float*)d_in[10];
    const float* bk2 = (const float*)d_in[11];
    const float* Wv2 = (const float*)d_in[12];
    const float* bv2 = (const float*)d_in[13];
    const float* gamma = (const float*)d_in[14];
    float* out = (float*)d_out;

    const int smP_bytes = (64 + 128) * PAP * (int)sizeof(__half);
    const int smL_bytes = 2 * 128 * LP * (int)sizeof(__half);
    const int smO_bytes = 3 * STAGE * (int)sizeof(__half);   // 110592 B -> 2 CTA/SM
    static bool attr_done = false;
    if (!attr_done) {
        cudaFuncSetAttribute(proj_mma,   cudaFuncAttributeMaxDynamicSharedMemorySize, smP_bytes);
        cudaFuncSetAttribute(logits_mma, cudaFuncAttributeMaxDynamicSharedMemorySize, smL_bytes);
        cudaFuncSetAttribute(out_mma,    cudaFuncAttributeMaxDynamicSharedMemorySize, smO_bytes);
        attr_done = true;
    }

    void* rs_addr = nullptr;
    cudaGetSymbolAddress(&rs_addr, g_rowsum);
    cudaMemsetAsync(rs_addr, 0, 4 * HWs * sizeof(float));

    xt_kernel<<<dim3(128, 8, 4), 256>>>(input1, input2);
    proj_mma<<<dim3(32, 7, 4), 256, smP_bytes>>>(
        Wq1, bq1, Wk1, bk1, Wv1, bv1,
        Wq2, bq2, Wk2, bk2, Wv2, bv2);
    logits_mma<<<dim3(32, 32, 4), 256, smL_bytes>>>();
    out_mma<<<dim3(32, 2, 4), 256, smO_bytes>>>(input1, input2, gamma, out);
}

// round 14
// speedup vs baseline: 1.0819x; 1.0819x over previous
#include <cuda_runtime.h>
#include <cuda_fp16.h>
#include <cstdint>

#define HWs 4096
#define Cc  256
#define NB  2

// ---------------- scratch (fp16) ------------------------------------------------
__device__ __align__(256) __half g_xt[4][HWs][Cc];
__device__ __align__(256) __half g_q[NB][HWs][128];
__device__ __align__(256) __half g_k[NB][2][HWs][128];
__device__ __align__(256) __half g_v[NB][2][Cc][HWs];
__device__ __align__(256) __half g_P[4][HWs][HWs];      // unnormalized exp(S)
__device__ __align__(256) float g_rowsum[4][HWs];

// ---------------- helpers --------------------------------------------------------
__device__ __forceinline__ uint32_t smem_u32(const void* p) {
    uint32_t a;
    asm("{ .reg .u64 t; cvta.to.shared.u64 t, %1; cvt.u32.u64 %0, t; }"
        : "=r"(a) : "l"(p));
    return a;
}
__device__ __forceinline__ void ldmatrix_x4(uint32_t* r, uint32_t addr) {
    asm volatile("ldmatrix.sync.aligned.m8n8.x4.shared.b16 {%0,%1,%2,%3}, [%4];"
        : "=r"(r[0]), "=r"(r[1]), "=r"(r[2]), "=r"(r[3]) : "r"(addr));
}
__device__ __forceinline__ void mma_f32(float* d, const uint32_t* a,
                                        uint32_t b0, uint32_t b1) {
    asm volatile(
        "mma.sync.aligned.m16n8k16.row.col.f32.f16.f16.f32 "
        "{%0,%1,%2,%3}, {%4,%5,%6,%7}, {%8,%9}, {%0,%1,%2,%3};"
        : "+f"(d[0]), "+f"(d[1]), "+f"(d[2]), "+f"(d[3])
        : "r"(a[0]), "r"(a[1]), "r"(a[2]), "r"(a[3]), "r"(b0), "r"(b1));
}
__device__ __forceinline__ void mma_f16(uint32_t* d, const uint32_t* a,
                                        uint32_t b0, uint32_t b1) {
    asm volatile(
        "mma.sync.aligned.m16n8k16.row.col.f16.f16.f16.f16 "
        "{%0,%1}, {%2,%3,%4,%5}, {%6,%7}, {%0,%1};"
        : "+r"(d[0]), "+r"(d[1])
        : "r"(a[0]), "r"(a[1]), "r"(a[2]), "r"(a[3]), "r"(b0), "r"(b1));
}
#define CP_ASYNC16(dst, src) \
    asm volatile("cp.async.cg.shared.global [%0], [%1], 16;" :: "r"(dst), "l"(src))

#define MBARRIER_INIT(mb, c) \
    asm volatile("mbarrier.init.shared.b64 [%0], %1;" :: "r"((uint32_t)(mb)), "r"((uint32_t)(c)) : "memory")
#define MBAR_ARRIVE(mb) \
    asm volatile("mbarrier.arrive.shared.b64 _, [%0];" :: "r"((uint32_t)(mb)) : "memory")
// NOTE: .noinc is load-bearing — default variant nets to zero and deadlocks.
#define CP_ASYNC_MBAR_ARRIVE_NOINC(mb) \
    asm volatile("cp.async.mbarrier.arrive.noinc.shared.b64 [%0];" :: "r"((uint32_t)(mb)) : "memory")

#define MBARRIER_WAIT_PARITY(mb, ph) do { \
    uint32_t _mb = (uint32_t)(mb); uint32_t _p = (uint32_t)(ph); uint32_t _done; \
    asm volatile("{\n\t.reg .pred p;\n\t" \
        "mbarrier.try_wait.parity.acquire.cta.shared::cta.b64 p, [%1], %2;\n\t" \
        "selp.b32 %0, 1, 0, p;\n\t}" : "=r"(_done) : "r"(_mb), "r"(_p) : "memory"); \
    if (!_done) { \
        asm volatile("{\n\t.reg .pred P1;\n\t" \
            "WAIT_LOOP_%=:\n\t" \
            "mbarrier.try_wait.parity.acquire.cta.shared::cta.b64 P1, [%0], %1, 0x989680;\n\t" \
            "@P1 bra.uni WAIT_DONE_%=;\n\t" \
            "bra.uni WAIT_LOOP_%=;\n\t" \
            "WAIT_DONE_%=:\n\t}" :: "r"(_mb), "r"(_p) : "memory"); \
    } \
} while (0)

__device__ __forceinline__ uint32_t pack_h2(float a, float b) {
    __half2 h = __floats2half2_rn(a, b);
    return *reinterpret_cast<uint32_t*>(&h);
}
__device__ __forceinline__ float2 unpack_h2(uint32_t w) {
    return __half22float2(*reinterpret_cast<__half2*>(&w));
}

// ---------------------------------------------------------------------------
// Stage 0: transpose+convert x -> g_xt[t][n][c] fp16.  grid (128, 8, 4)
// ---------------------------------------------------------------------------
__global__ __launch_bounds__(256) void xt_kernel(
    const float* __restrict__ x1, const float* __restrict__ x2)
{
    const int t = blockIdx.z;
    const int br = t >> 1, b = t & 1;
    const float* src = (br ? x2 : x1) + (size_t)b * Cc * HWs;

    const int n0 = blockIdx.x * 32;
    const int c0 = blockIdx.y * 32;

    __shared__ float tile[32][33];
    const int tx = threadIdx.x & 31;
    const int ty = threadIdx.x >> 5;

    #pragma unroll
    for (int j = 0; j < 4; j++) {
        const int cl = ty * 4 + j;
        tile[cl][tx] = src[(size_t)(c0 + cl) * HWs + n0 + tx];
    }
    __syncthreads();
    #pragma unroll
    for (int j = 0; j < 4; j++) {
        const int nl = ty * 4 + j;
        g_xt[t][n0 + nl][c0 + tx] = __float2half(tile[tx][nl]);
    }
}

// ---------------------------------------------------------------------------
// Stage A: projections via fp16 mma (f16 accum).  (unchanged)
// ---------------------------------------------------------------------------
#define PAP 264

__global__ __launch_bounds__(256) void proj_mma(
    const float* __restrict__ Wq1, const float* __restrict__ bq1,
    const float* __restrict__ Wk1, const float* __restrict__ bk1,
    const float* __restrict__ Wv1, const float* __restrict__ bv1,
    const float* __restrict__ Wq2, const float* __restrict__ bq2,
    const float* __restrict__ Wk2, const float* __restrict__ bk2,
    const float* __restrict__ Wv2, const float* __restrict__ bv2)
{
    extern __shared__ __half smP[];
    __half* As = smP;
    __half* Bs = smP + 64 * PAP;

    const int combo = blockIdx.z;
    const int b  = combo >> 1;
    const int br = combo & 1;
    const int t  = br * 2 + b;

    const float* Wq = br ? Wq2 : Wq1;
    const float* Wk = br ? Wk2 : Wk1;
    const float* Wv = br ? Wv2 : Wv1;
    const float* bq = br ? bq2 : bq1;
    const float* bk = br ? bk2 : bk1;
    const float* bv = br ? bv2 : bv1;

    const int m0 = blockIdx.y * 64;
    const int n0 = blockIdx.x * 128;

    const int cls = (blockIdx.y == 0) ? 0 : (blockIdx.y < 3 ? 1 : 2);
    const float* Wbase = (cls == 0) ? Wq : (cls == 1 ? Wk : Wv);
    const int    roff  = (cls == 0) ? 0  : (cls == 1 ? 64 : 192);

    const int tid = threadIdx.x;

    #pragma unroll
    for (int s = 0; s < 16; s++) {
        const int i = tid + s * 256;
        const int r = i >> 6;
        const int c = (i & 63) * 4;
        float4 w4 = *reinterpret_cast<const float4*>(
            Wbase + (size_t)(m0 - roff + r) * Cc + c);
        uint2 v;
        v.x = pack_h2(w4.x, w4.y);
        v.y = pack_h2(w4.z, w4.w);
        *reinterpret_cast<uint2*>(&As[r * PAP + c]) = v;
    }
    #pragma unroll
    for (int s = 0; s < 16; s++) {
        const int i = tid + s * 256;
        const int r = i >> 5;
        const int c = (i & 31) * 8;
        uint4 v = *reinterpret_cast<const uint4*>(&g_xt[t][n0 + r][c]);
        *reinterpret_cast<uint4*>(&Bs[r * PAP + c]) = v;
    }
    __syncthreads();

    const int w = tid >> 5, l = tid & 31;
    const int wm = w >> 2, wn = w & 3;
    const int lrow = l & 15, lcol = (l >> 4) * 8;
    const uint32_t a_base = smem_u32(As + (wm * 32) * PAP);
    const uint32_t b_base = smem_u32(Bs + (wn * 32) * PAP);

    uint32_t acc[2][4][2];
    #pragma unroll
    for (int i = 0; i < 2; i++)
        #pragma unroll
        for (int j = 0; j < 4; j++) { acc[i][j][0] = 0u; acc[i][j][1] = 0u; }

    #pragma unroll
    for (int k = 0; k < 256; k += 16) {
        uint32_t af[2][4], bf[2][4];
        #pragma unroll
        for (int mi = 0; mi < 2; mi++)
            ldmatrix_x4(af[mi], a_base + ((mi * 16 + lrow) * PAP + k + lcol) * 2);
        #pragma unroll
        for (int nj = 0; nj < 2; nj++)
            ldmatrix_x4(bf[nj], b_base + ((nj * 16 + lrow) * PAP + k + lcol) * 2);
        #pragma unroll
        for (int mi = 0; mi < 2; mi++)
            #pragma unroll
            for (int ni = 0; ni < 4; ni++)
                mma_f16(acc[mi][ni], af[mi], bf[ni >> 1][ni & 1], bf[ni >> 1][(ni & 1) + 2]);
    }

    #pragma unroll
    for (int mi = 0; mi < 2; mi++) {
        const int r0 = wm * 32 + mi * 16 + (l >> 2);
        #pragma unroll
        for (int ni = 0; ni < 4; ni++) {
            const int n = n0 + wn * 32 + ni * 8 + (l & 3) * 2;
            float2 dlo = unpack_h2(acc[mi][ni][0]);
            float2 dhi = unpack_h2(acc[mi][ni][1]);
            if (cls == 0) {
                const int r = m0 + r0, r8 = r + 8;
                g_q[b][n][2 * r + br]      = __float2half(dlo.x + bq[r]);
                g_q[b][n + 1][2 * r + br]  = __float2half(dlo.y + bq[r]);
                g_q[b][n][2 * r8 + br]     = __float2half(dhi.x + bq[r8]);
                g_q[b][n + 1][2 * r8 + br] = __float2half(dhi.y + bq[r8]);
            } else if (cls == 1) {
                const int c = m0 - 64 + r0, c8 = c + 8;
                g_k[b][br][n][c]      = __float2half(dlo.x + bk[c]);
                g_k[b][br][n + 1][c]  = __float2half(dlo.y + bk[c]);
                g_k[b][br][n][c8]     = __float2half(dhi.x + bk[c8]);
                g_k[b][br][n + 1][c8] = __float2half(dhi.y + bk[c8]);
            } else {
                const int c = m0 - 192 + r0, c8 = c + 8;
                *reinterpret_cast<uint32_t*>(&g_v[b][br][c][n])  = pack_h2(dlo.x + bv[c],  dlo.y + bv[c]);
                *reinterpret_cast<uint32_t*>(&g_v[b][br][c8][n]) = pack_h2(dhi.x + bv[c8], dhi.y + bv[c8]);
            }
        }
    }
}

// ---------------------------------------------------------------------------
// Stage B: logits (f16 accum) -> exp(S) fp16 + row sums.
// WIDENED: block tile 128n x 256m (q reads halved, 4 MMA/ldmatrix).
// 8 warps (2n x 4m), warp tile 64n x 64m.  grid (16 m, 32 n, 4 combos)
// ---------------------------------------------------------------------------
#define LP  136    // q/k tile pitch (128 + 8)
#define LSP 264    // staging pitch (256 + 8)

__global__ __launch_bounds__(256) void logits_mma()
{
    extern __shared__ __half smL[];
    __half* As = smL;                 // q: [128][LP]
    __half* Bs = smL + 128 * LP;      // k: [256][LP]

    const int combo = blockIdx.z;
    const int b = combo >> 1, br = combo & 1;
    const int n0 = blockIdx.y * 128;
    const int m0 = blockIdx.x * 256;
    const int tid = threadIdx.x;

    #pragma unroll
    for (int s = 0; s < 8; s++) {                 // q: 2048 uint4
        const int i = tid + s * 256;
        const int r = i >> 4, c = i & 15;
        uint4 v = reinterpret_cast<const uint4*>(&g_q[b][n0 + r][0])[c];
        *reinterpret_cast<uint4*>(&As[r * LP + c * 8]) = v;
    }
    #pragma unroll
    for (int s = 0; s < 16; s++) {                // k: 4096 uint4
        const int i = tid + s * 256;
        const int r = i >> 4, c = i & 15;
        uint4 v = reinterpret_cast<const uint4*>(&g_k[b][br][m0 + r][0])[c];
        *reinterpret_cast<uint4*>(&Bs[r * LP + c * 8]) = v;
    }
    __syncthreads();

    const int w = tid >> 5, l = tid & 31;
    const int wn = w >> 2, wm = w & 3;            // 2n x 4m
    const uint32_t a_base = smem_u32(As + (wn * 64) * LP);
    const uint32_t b_base = smem_u32(Bs + (wm * 64) * LP);
    const int lrow = l & 15, lcol = (l >> 4) * 8;

    uint32_t acc[4][8][2];                         // 64n x 64m, f16 accum
    #pragma unroll
    for (int i = 0; i < 4; i++)
        #pragma unroll
        for (int j = 0; j < 8; j++) { acc[i][j][0] = 0u; acc[i][j][1] = 0u; }

    #pragma unroll
    for (int k = 0; k < 128; k += 16) {
        uint32_t af[4][4], bf[4][4];
        #pragma unroll
        for (int mi = 0; mi < 4; mi++)
            ldmatrix_x4(af[mi], a_base + ((mi * 16 + lrow) * LP + k + lcol) * 2);
        #pragma unroll
        for (int nj = 0; nj < 4; nj++)
            ldmatrix_x4(bf[nj], b_base + ((nj * 16 + lrow) * LP + k + lcol) * 2);
        #pragma unroll
        for (int mi = 0; mi < 4; mi++)
            #pragma unroll
            for (int ni = 0; ni < 8; ni++)
                mma_f16(acc[mi][ni], af[mi], bf[ni >> 1][ni & 1], bf[ni >> 1][(ni & 1) + 2]);
    }

    // exp, stage to smem [128][LSP], coalesced store + row sums
    __syncthreads();
    __half* St = As;                              // reuse (67.6KB < 104KB)
    const int nbl = wn * 64 + (l >> 2);
    const int mbl = wm * 64 + (l & 3) * 2;
    #pragma unroll
    for (int mi = 0; mi < 4; mi++) {
        #pragma unroll
        for (int ni = 0; ni < 8; ni++) {
            float2 dlo = unpack_h2(acc[mi][ni][0]);
            float2 dhi = unpack_h2(acc[mi][ni][1]);
            *reinterpret_cast<uint32_t*>(&St[(nbl + mi * 16) * LSP + mbl + ni * 8]) =
                pack_h2(__expf(dlo.x), __expf(dlo.y));
            *reinterpret_cast<uint32_t*>(&St[(nbl + mi * 16 + 8) * LSP + mbl + ni * 8]) =
                pack_h2(__expf(dhi.x), __expf(dhi.y));
        }
    }
    __syncthreads();

    #pragma unroll
    for (int s = 0; s < 16; s++) {                // 128 rows x 32 uint4
        const int i = tid + s * 256;
        const int r = i >> 5, c = (i & 31) * 8;
        uint4 v = *reinterpret_cast<const uint4*>(&St[r * LSP + c]);
        *reinterpret_cast<uint4*>(&g_P[combo][n0 + r][m0 + c]) = v;
    }

    {
        const int r = tid >> 1;
        const int half = tid & 1;
        const uint32_t* row = reinterpret_cast<const uint32_t*>(&St[r * LSP + half * 128]);
        float s = 0.0f;
        #pragma unroll
        for (int j = 0; j < 64; j++) {
            float2 p = unpack_h2(row[j]);
            s += p.x + p.y;
        }
        s += __shfl_xor_sync(0xffffffffu, s, 1);
        if (half == 0) atomicAdd(&g_rowsum[combo][n0 + r], s);
    }
}

// ---------------------------------------------------------------------------
// Stage D: out = (gamma/rowsum[n]) * (expS @ V^T) + x.  (exact R11 version)
// 4-stage mbarrier ring, no __syncthreads in mainloop, 8 warps 64c x 64n.
// grid (32 n, 4 combos) = 128 blocks = 1 wave.
// ---------------------------------------------------------------------------
#define OPITCH 72
#define AH     (256 * OPITCH)
#define STAGE  (384 * OPITCH)
#define NKT    64

__global__ __launch_bounds__(256, 1) void out_mma(
    const float* __restrict__ x1, const float* __restrict__ x2,
    const float* __restrict__ gamma, float* __restrict__ out)
{
    extern __shared__ __half smO[];     // [4][STAGE]
    __shared__ __align__(8) uint64_t s_full[4];
    __shared__ __align__(8) uint64_t s_empty[4];

    const int combo = blockIdx.y;
    const int b = combo >> 1, br = combo & 1;
    const int n0 = blockIdx.x * 128;
    const int tid = threadIdx.x;

    if (tid == 0) {
        #pragma unroll
        for (int s = 0; s < 4; s++) {
            MBARRIER_INIT(smem_u32(&s_full[s]), 256);
            MBARRIER_INIT(smem_u32(&s_empty[s]), 256);
        }
    }
    __syncthreads();

    const __half* Vb = &g_v[b][br][0][0];
    const __half* Pb = &g_P[combo][n0][0];

    auto produce = [&](int p) {
        const int st = p & 3;
        if (p >= 4) {
            MBARRIER_WAIT_PARITY(smem_u32(&s_empty[st]), ((p >> 2) - 1) & 1);
        }
        __half* base = smO + st * STAGE;
        const int k0 = p * 64;
        #pragma unroll
        for (int s = 0; s < 8; s++) {
            const int i = tid + s * 256;
            const int r = i >> 3, c = (i & 7) * 8;
            CP_ASYNC16(smem_u32(base + r * OPITCH + c),
                       Vb + (size_t)r * HWs + k0 + c);
        }
        #pragma unroll
        for (int s = 0; s < 4; s++) {
            const int i = tid + s * 256;
            const int r = i >> 3, c = (i & 7) * 8;
            CP_ASYNC16(smem_u32(base + AH + r * OPITCH + c),
                       Pb + (size_t)r * HWs + k0 + c);
        }
        CP_ASYNC_MBAR_ARRIVE_NOINC(smem_u32(&s_full[st]));
    };

    const int w = tid >> 5, l = tid & 31;
    const int wc = w >> 1, wn = w & 1;
    const int lrow = l & 15, lcol = (l >> 4) * 8;

    float acc[4][8][4];
    #pragma unroll
    for (int i = 0; i < 4; i++)
        #pragma unroll
        for (int j = 0; j < 8; j++)
            #pragma unroll
            for (int q = 0; q < 4; q++) acc[i][j][q] = 0.0f;

    produce(0);
    produce(1);

    for (int kt = 0; kt < NKT; kt++) {
        const int st = kt & 3;
        MBARRIER_WAIT_PARITY(smem_u32(&s_full[st]), (kt >> 2) & 1);
        if (kt + 2 < NKT) produce(kt + 2);

        const __half* base = smO + st * STAGE;
        const uint32_t a_base = smem_u32(base + (wc * 64) * OPITCH);
        const uint32_t b_base = smem_u32(base + AH + (wn * 64) * OPITCH);

        #pragma unroll
        for (int k = 0; k < 64; k += 16) {
            uint32_t af[4][4], bf[4][4];
            #pragma unroll
            for (int mi = 0; mi < 4; mi++)
                ldmatrix_x4(af[mi], a_base + ((mi * 16 + lrow) * OPITCH + k + lcol) * 2);
            #pragma unroll
            for (int nj = 0; nj < 4; nj++)
                ldmatrix_x4(bf[nj], b_base + ((nj * 16 + lrow) * OPITCH + k + lcol) * 2);
            #pragma unroll
            for (int mi = 0; mi < 4; mi++)
                #pragma unroll
                for (int ni = 0; ni < 8; ni++)
                    mma_f32(acc[mi][ni], af[mi],
                            bf[ni >> 1][ni & 1], bf[ni >> 1][(ni & 1) + 2]);
        }
        MBAR_ARRIVE(smem_u32(&s_empty[st]));
    }

    const float g = gamma[0];
    const float* x = (br ? x2 : x1) + (size_t)b * Cc * HWs;
    float* ob = out + (size_t)(br * 2 + b) * Cc * HWs;

    const int cb = wc * 64 + (l >> 2);
    const int nb = n0 + wn * 64 + (l & 3) * 2;
    #pragma unroll
    for (int ni = 0; ni < 8; ni++) {
        const int n = nb + ni * 8;
        float2 rs = *reinterpret_cast<const float2*>(&g_rowsum[combo][n]);
        const float s0 = __fdividef(g, rs.x);
        const float s1 = __fdividef(g, rs.y);
        #pragma unroll
        for (int mi = 0; mi < 4; mi++) {
            const int c = cb + mi * 16;
            {
                float2 xi = *reinterpret_cast<const float2*>(x + (size_t)c * HWs + n);
                float2 o;
                o.x = fmaf(s0, acc[mi][ni][0], xi.x);
                o.y = fmaf(s1, acc[mi][ni][1], xi.y);
                *reinterpret_cast<float2*>(ob + (size_t)c * HWs + n) = o;
            }
            {
                float2 xi = *reinterpret_cast<const float2*>(x + (size_t)(c + 8) * HWs + n);
                float2 o;
                o.x = fmaf(s0, acc[mi][ni][2], xi.x);
                o.y = fmaf(s1, acc[mi][ni][3], xi.y);
                *reinterpret_cast<float2*>(ob + (size_t)(c + 8) * HWs + n) = o;
            }
        }
    }
}

// ---------------------------------------------------------------------------
extern "C" void kernel_launch(void* const* d_in, const int* in_sizes, int n_in,
                              void* d_out, int out_size)
{
    const float* input1 = (const float*)d_in[0];
    const float* input2 = (const float*)d_in[1];
    const float* Wq1 = (const float*)d_in[2];
    const float* bq1 = (const float*)d_in[3];
    const float* Wk1 = (const float*)d_in[4];
    const float* bk1 = (const float*)d_in[5];
    const float* Wv1 = (const float*)d_in[6];
    const float* bv1 = (const float*)d_in[7];
    const float* Wq2 = (const float*)d_in[8];
    const float* bq2 = (const float*)d_in[9];
    const float* Wk2 = (const float*)d_in[10];
    const float* bk2 = (const float*)d_in[11];
    const float* Wv2 = (const float*)d_in[12];
    const float* bv2 = (const float*)d_in[13];
    const float* gamma = (const float*)d_in[14];
    float* out = (float*)d_out;

    const int smP_bytes = (64 + 128) * PAP * (int)sizeof(__half);
    const int smL_bytes = (128 + 256) * LP * (int)sizeof(__half);    // 104448
    const int smO_bytes = 4 * STAGE * (int)sizeof(__half);           // 221184
    static bool attr_done = false;
    if (!attr_done) {
        cudaFuncSetAttribute(proj_mma,   cudaFuncAttributeMaxDynamicSharedMemorySize, smP_bytes);
        cudaFuncSetAttribute(logits_mma, cudaFuncAttributeMaxDynamicSharedMemorySize, smL_bytes);
        cudaFuncSetAttribute(out_mma,    cudaFuncAttributeMaxDynamicSharedMemorySize, smO_bytes);
        attr_done = true;
    }

    void* rs_addr = nullptr;
    cudaGetSymbolAddress(&rs_addr, g_rowsum);
    cudaMemsetAsync(rs_addr, 0, 4 * HWs * sizeof(float));

    xt_kernel<<<dim3(128, 8, 4), 256>>>(input1, input2);
    proj_mma<<<dim3(32, 7, 4), 256, smP_bytes>>>(
        Wq1, bq1, Wk1, bk1, Wv1, bv1,
        Wq2, bq2, Wk2, bk2, Wv2, bv2);
    logits_mma<<<dim3(16, 32, 4), 256, smL_bytes>>>();
    out_mma<<<dim3(32, 4), 256, smO_bytes>>>(input1, input2, gamma, out);
}

// round 15
// speedup vs baseline: 1.0905x; 1.0079x over previous
#include <cuda_runtime.h>
#include <cuda_fp16.h>
#include <cuda_fp8.h>
#include <cstdint>

#define HWs 4096
#define Cc  256
#define NB  2

// ---------------- scratch -------------------------------------------------------
__device__ __align__(256) __half g_xt[4][HWs][Cc];
__device__ __align__(256) __half g_q[NB][HWs][128];
__device__ __align__(256) __half g_k[NB][2][HWs][128];
__device__ __align__(256) uint8_t g_v8[NB][2][Cc][HWs];   // V in e4m3
__device__ __align__(256) uint8_t g_P8[4][HWs][HWs];      // exp(S-6) in e4m3
__device__ __align__(256) float g_rowsum[4][HWs];

// ---------------- helpers --------------------------------------------------------
__device__ __forceinline__ uint32_t smem_u32(const void* p) {
    uint32_t a;
    asm("{ .reg .u64 t; cvta.to.shared.u64 t, %1; cvt.u32.u64 %0, t; }"
        : "=r"(a) : "l"(p));
    return a;
}
__device__ __forceinline__ void ldmatrix_x4(uint32_t* r, uint32_t addr) {
    asm volatile("ldmatrix.sync.aligned.m8n8.x4.shared.b16 {%0,%1,%2,%3}, [%4];"
        : "=r"(r[0]), "=r"(r[1]), "=r"(r[2]), "=r"(r[3]) : "r"(addr));
}
__device__ __forceinline__ void mma_fp8(float* d, const uint32_t* a,
                                        uint32_t b0, uint32_t b1) {
    asm volatile(
        "mma.sync.aligned.m16n8k32.row.col.f32.e4m3.e4m3.f32 "
        "{%0,%1,%2,%3}, {%4,%5,%6,%7}, {%8,%9}, {%0,%1,%2,%3};"
        : "+f"(d[0]), "+f"(d[1]), "+f"(d[2]), "+f"(d[3])
        : "r"(a[0]), "r"(a[1]), "r"(a[2]), "r"(a[3]), "r"(b0), "r"(b1));
}
__device__ __forceinline__ void mma_f16(uint32_t* d, const uint32_t* a,
                                        uint32_t b0, uint32_t b1) {
    asm volatile(
        "mma.sync.aligned.m16n8k16.row.col.f16.f16.f16.f16 "
        "{%0,%1}, {%2,%3,%4,%5}, {%6,%7}, {%0,%1};"
        : "+r"(d[0]), "+r"(d[1])
        : "r"(a[0]), "r"(a[1]), "r"(a[2]), "r"(a[3]), "r"(b0), "r"(b1));
}
#define CP_ASYNC16(dst, src) \
    asm volatile("cp.async.cg.shared.global [%0], [%1], 16;" :: "r"(dst), "l"(src))

#define MBARRIER_INIT(mb, c) \
    asm volatile("mbarrier.init.shared.b64 [%0], %1;" :: "r"((uint32_t)(mb)), "r"((uint32_t)(c)) : "memory")
#define MBAR_ARRIVE(mb) \
    asm volatile("mbarrier.arrive.shared.b64 _, [%0];" :: "r"((uint32_t)(mb)) : "memory")
// NOTE: .noinc is load-bearing — default variant nets to zero and deadlocks.
#define CP_ASYNC_MBAR_ARRIVE_NOINC(mb) \
    asm volatile("cp.async.mbarrier.arrive.noinc.shared.b64 [%0];" :: "r"((uint32_t)(mb)) : "memory")

#define MBARRIER_WAIT_PARITY(mb, ph) do { \
    uint32_t _mb = (uint32_t)(mb); uint32_t _p = (uint32_t)(ph); uint32_t _done; \
    asm volatile("{\n\t.reg .pred p;\n\t" \
        "mbarrier.try_wait.parity.acquire.cta.shared::cta.b64 p, [%1], %2;\n\t" \
        "selp.b32 %0, 1, 0, p;\n\t}" : "=r"(_done) : "r"(_mb), "r"(_p) : "memory"); \
    if (!_done) { \
        asm volatile("{\n\t.reg .pred P1;\n\t" \
            "WAIT_LOOP_%=:\n\t" \
            "mbarrier.try_wait.parity.acquire.cta.shared::cta.b64 P1, [%0], %1, 0x989680;\n\t" \
            "@P1 bra.uni WAIT_DONE_%=;\n\t" \
            "bra.uni WAIT_LOOP_%=;\n\t" \
            "WAIT_DONE_%=:\n\t}" :: "r"(_mb), "r"(_p) : "memory"); \
    } \
} while (0)

__device__ __forceinline__ uint32_t pack_h2(float a, float b) {
    __half2 h = __floats2half2_rn(a, b);
    return *reinterpret_cast<uint32_t*>(&h);
}
__device__ __forceinline__ float2 unpack_h2(uint32_t w) {
    return __half22float2(*reinterpret_cast<__half2*>(&w));
}
__device__ __forceinline__ uint16_t pack_fp8x2(float a, float b) {
    return (uint16_t)__nv_cvt_float2_to_fp8x2(make_float2(a, b),
                                              __NV_SATFINITE, __NV_E4M3);
}
__device__ __forceinline__ uint16_t h2_to_fp8x2(__half2 h) {
    __half2_raw hr = *reinterpret_cast<__half2_raw*>(&h);
    return (uint16_t)__nv_cvt_halfraw2_to_fp8x2(hr, __NV_SATFINITE, __NV_E4M3);
}

// ---------------------------------------------------------------------------
// Stage 0: transpose+convert x -> g_xt[t][n][c] fp16.  grid (128, 8, 4)
// ---------------------------------------------------------------------------
__global__ __launch_bounds__(256) void xt_kernel(
    const float* __restrict__ x1, const float* __restrict__ x2)
{
    const int t = blockIdx.z;
    const int br = t >> 1, b = t & 1;
    const float* src = (br ? x2 : x1) + (size_t)b * Cc * HWs;

    const int n0 = blockIdx.x * 32;
    const int c0 = blockIdx.y * 32;

    __shared__ float tile[32][33];
    const int tx = threadIdx.x & 31;
    const int ty = threadIdx.x >> 5;

    #pragma unroll
    for (int j = 0; j < 4; j++) {
        const int cl = ty * 4 + j;
        tile[cl][tx] = src[(size_t)(c0 + cl) * HWs + n0 + tx];
    }
    __syncthreads();
    #pragma unroll
    for (int j = 0; j < 4; j++) {
        const int nl = ty * 4 + j;
        g_xt[t][n0 + nl][c0 + tx] = __float2half(tile[tx][nl]);
    }
}

// ---------------------------------------------------------------------------
// Stage A: projections via fp16 mma (f16 accum).  v -> e4m3.
// ---------------------------------------------------------------------------
#define PAP 264

__global__ __launch_bounds__(256) void proj_mma(
    const float* __restrict__ Wq1, const float* __restrict__ bq1,
    const float* __restrict__ Wk1, const float* __restrict__ bk1,
    const float* __restrict__ Wv1, const float* __restrict__ bv1,
    const float* __restrict__ Wq2, const float* __restrict__ bq2,
    const float* __restrict__ Wk2, const float* __restrict__ bk2,
    const float* __restrict__ Wv2, const float* __restrict__ bv2)
{
    extern __shared__ __half smP[];
    __half* As = smP;
    __half* Bs = smP + 64 * PAP;

    const int combo = blockIdx.z;
    const int b  = combo >> 1;
    const int br = combo & 1;
    const int t  = br * 2 + b;

    const float* Wq = br ? Wq2 : Wq1;
    const float* Wk = br ? Wk2 : Wk1;
    const float* Wv = br ? Wv2 : Wv1;
    const float* bq = br ? bq2 : bq1;
    const float* bk = br ? bk2 : bk1;
    const float* bv = br ? bv2 : bv1;

    const int m0 = blockIdx.y * 64;
    const int n0 = blockIdx.x * 128;

    const int cls = (blockIdx.y == 0) ? 0 : (blockIdx.y < 3 ? 1 : 2);
    const float* Wbase = (cls == 0) ? Wq : (cls == 1 ? Wk : Wv);
    const int    roff  = (cls == 0) ? 0  : (cls == 1 ? 64 : 192);

    const int tid = threadIdx.x;

    #pragma unroll
    for (int s = 0; s < 16; s++) {
        const int i = tid + s * 256;
        const int r = i >> 6;
        const int c = (i & 63) * 4;
        float4 w4 = *reinterpret_cast<const float4*>(
            Wbase + (size_t)(m0 - roff + r) * Cc + c);
        uint2 v;
        v.x = pack_h2(w4.x, w4.y);
        v.y = pack_h2(w4.z, w4.w);
        *reinterpret_cast<uint2*>(&As[r * PAP + c]) = v;
    }
    #pragma unroll
    for (int s = 0; s < 16; s++) {
        const int i = tid + s * 256;
        const int r = i >> 5;
        const int c = (i & 31) * 8;
        uint4 v = *reinterpret_cast<const uint4*>(&g_xt[t][n0 + r][c]);
        *reinterpret_cast<uint4*>(&Bs[r * PAP + c]) = v;
    }
    __syncthreads();

    const int w = tid >> 5, l = tid & 31;
    const int wm = w >> 2, wn = w & 3;
    const int lrow = l & 15, lcol = (l >> 4) * 8;
    const uint32_t a_base = smem_u32(As + (wm * 32) * PAP);
    const uint32_t b_base = smem_u32(Bs + (wn * 32) * PAP);

    uint32_t acc[2][4][2];
    #pragma unroll
    for (int i = 0; i < 2; i++)
        #pragma unroll
        for (int j = 0; j < 4; j++) { acc[i][j][0] = 0u; acc[i][j][1] = 0u; }

    #pragma unroll
    for (int k = 0; k < 256; k += 16) {
        uint32_t af[2][4], bf[2][4];
        #pragma unroll
        for (int mi = 0; mi < 2; mi++)
            ldmatrix_x4(af[mi], a_base + ((mi * 16 + lrow) * PAP + k + lcol) * 2);
        #pragma unroll
        for (int nj = 0; nj < 2; nj++)
            ldmatrix_x4(bf[nj], b_base + ((nj * 16 + lrow) * PAP + k + lcol) * 2);
        #pragma unroll
        for (int mi = 0; mi < 2; mi++)
            #pragma unroll
            for (int ni = 0; ni < 4; ni++)
                mma_f16(acc[mi][ni], af[mi], bf[ni >> 1][ni & 1], bf[ni >> 1][(ni & 1) + 2]);
    }

    #pragma unroll
    for (int mi = 0; mi < 2; mi++) {
        const int r0 = wm * 32 + mi * 16 + (l >> 2);
        #pragma unroll
        for (int ni = 0; ni < 4; ni++) {
            const int n = n0 + wn * 32 + ni * 8 + (l & 3) * 2;
            float2 dlo = unpack_h2(acc[mi][ni][0]);
            float2 dhi = unpack_h2(acc[mi][ni][1]);
            if (cls == 0) {
                const int r = m0 + r0, r8 = r + 8;
                g_q[b][n][2 * r + br]      = __float2half(dlo.x + bq[r]);
                g_q[b][n + 1][2 * r + br]  = __float2half(dlo.y + bq[r]);
                g_q[b][n][2 * r8 + br]     = __float2half(dhi.x + bq[r8]);
                g_q[b][n + 1][2 * r8 + br] = __float2half(dhi.y + bq[r8]);
            } else if (cls == 1) {
                const int c = m0 - 64 + r0, c8 = c + 8;
                g_k[b][br][n][c]      = __float2half(dlo.x + bk[c]);
                g_k[b][br][n + 1][c]  = __float2half(dlo.y + bk[c]);
                g_k[b][br][n][c8]     = __float2half(dhi.x + bk[c8]);
                g_k[b][br][n + 1][c8] = __float2half(dhi.y + bk[c8]);
            } else {
                const int c = m0 - 192 + r0, c8 = c + 8;
                *reinterpret_cast<uint16_t*>(&g_v8[b][br][c][n]) =
                    pack_fp8x2(dlo.x + bv[c], dlo.y + bv[c]);
                *reinterpret_cast<uint16_t*>(&g_v8[b][br][c8][n]) =
                    pack_fp8x2(dhi.x + bv[c8], dhi.y + bv[c8]);
            }
        }
    }
}

// ---------------------------------------------------------------------------
// Stage B: logits (f16 accum) -> exp(S-6) e4m3 + row sums.
// Block tile 128n x 256m; 8 warps (2n x 4m), warp tile 64n x 64m.
// grid (16 m, 32 n, 4 combos)
// ---------------------------------------------------------------------------
#define LP  136
#define LSP 264

__global__ __launch_bounds__(256) void logits_mma()
{
    extern __shared__ __half smL[];
    __half* As = smL;                 // q: [128][LP]
    __half* Bs = smL + 128 * LP;      // k: [256][LP]

    const int combo = blockIdx.z;
    const int b = combo >> 1, br = combo & 1;
    const int n0 = blockIdx.y * 128;
    const int m0 = blockIdx.x * 256;
    const int tid = threadIdx.x;

    #pragma unroll
    for (int s = 0; s < 8; s++) {
        const int i = tid + s * 256;
        const int r = i >> 4, c = i & 15;
        uint4 v = reinterpret_cast<const uint4*>(&g_q[b][n0 + r][0])[c];
        *reinterpret_cast<uint4*>(&As[r * LP + c * 8]) = v;
    }
    #pragma unroll
    for (int s = 0; s < 16; s++) {
        const int i = tid + s * 256;
        const int r = i >> 4, c = i & 15;
        uint4 v = reinterpret_cast<const uint4*>(&g_k[b][br][m0 + r][0])[c];
        *reinterpret_cast<uint4*>(&Bs[r * LP + c * 8]) = v;
    }
    __syncthreads();

    const int w = tid >> 5, l = tid & 31;
    const int wn = w >> 2, wm = w & 3;
    const uint32_t a_base = smem_u32(As + (wn * 64) * LP);
    const uint32_t b_base = smem_u32(Bs + (wm * 64) * LP);
    const int lrow = l & 15, lcol = (l >> 4) * 8;

    uint32_t acc[4][8][2];
    #pragma unroll
    for (int i = 0; i < 4; i++)
        #pragma unroll
        for (int j = 0; j < 8; j++) { acc[i][j][0] = 0u; acc[i][j][1] = 0u; }

    #pragma unroll
    for (int k = 0; k < 128; k += 16) {
        uint32_t af[4][4], bf[4][4];
        #pragma unroll
        for (int mi = 0; mi < 4; mi++)
            ldmatrix_x4(af[mi], a_base + ((mi * 16 + lrow) * LP + k + lcol) * 2);
        #pragma unroll
        for (int nj = 0; nj < 4; nj++)
            ldmatrix_x4(bf[nj], b_base + ((nj * 16 + lrow) * LP + k + lcol) * 2);
        #pragma unroll
        for (int mi = 0; mi < 4; mi++)
            #pragma unroll
            for (int ni = 0; ni < 8; ni++)
                mma_f16(acc[mi][ni], af[mi], bf[ni >> 1][ni & 1], bf[ni >> 1][(ni & 1) + 2]);
    }

    // exp(S-6) to fp16 staging, then fp8 store + fp16-based row sums
    __syncthreads();
    __half* St = As;
    const int nbl = wn * 64 + (l >> 2);
    const int mbl = wm * 64 + (l & 3) * 2;
    #pragma unroll
    for (int mi = 0; mi < 4; mi++) {
        #pragma unroll
        for (int ni = 0; ni < 8; ni++) {
            float2 dlo = unpack_h2(acc[mi][ni][0]);
            float2 dhi = unpack_h2(acc[mi][ni][1]);
            *reinterpret_cast<uint32_t*>(&St[(nbl + mi * 16) * LSP + mbl + ni * 8]) =
                pack_h2(__expf(dlo.x - 6.0f), __expf(dlo.y - 6.0f));
            *reinterpret_cast<uint32_t*>(&St[(nbl + mi * 16 + 8) * LSP + mbl + ni * 8]) =
                pack_h2(__expf(dhi.x - 6.0f), __expf(dhi.y - 6.0f));
        }
    }
    __syncthreads();

    // store P as e4m3: 128 rows x 256 bytes
    #pragma unroll
    for (int s = 0; s < 16; s++) {
        const int i = tid + s * 256;
        const int r = i >> 5, c = (i & 31) * 8;
        uint4 v = *reinterpret_cast<const uint4*>(&St[r * LSP + c]);
        const __half2* hp = reinterpret_cast<const __half2*>(&v);
        uint2 o;
        o.x = (uint32_t)h2_to_fp8x2(hp[0]) | ((uint32_t)h2_to_fp8x2(hp[1]) << 16);
        o.y = (uint32_t)h2_to_fp8x2(hp[2]) | ((uint32_t)h2_to_fp8x2(hp[3]) << 16);
        *reinterpret_cast<uint2*>(&g_P8[combo][n0 + r][m0 + c]) = o;
    }

    {
        const int r = tid >> 1;
        const int half = tid & 1;
        const uint32_t* row = reinterpret_cast<const uint32_t*>(&St[r * LSP + half * 128]);
        float s = 0.0f;
        #pragma unroll
        for (int j = 0; j < 64; j++) {
            float2 p = unpack_h2(row[j]);
            s += p.x + p.y;
        }
        s += __shfl_xor_sync(0xffffffffu, s, 1);
        if (half == 0) atomicAdd(&g_rowsum[combo][n0 + r], s);
    }
}

// ---------------------------------------------------------------------------
// Stage D: out = (gamma/rowsum[n]) * (expS @ V^T) + x.  FP8 QMMA version.
// Block tile 256c x 128n, K-chunk 128 elements (128B rows, pitch 144B).
// 4-stage mbarrier ring, no __syncthreads in mainloop, 8 warps 64c x 64n.
// grid (32 n, 4 combos) = 128 blocks = 1 wave.  NKT = 32.
// ---------------------------------------------------------------------------
#define OPB    144                      // stage row pitch in BYTES
#define AHB    (256 * OPB)              // V bytes per stage
#define STAGEB (384 * OPB)              // stage bytes (V + P)
#define NKT    32                       // 4096 / 128

__global__ __launch_bounds__(256, 1) void out_mma(
    const float* __restrict__ x1, const float* __restrict__ x2,
    const float* __restrict__ gamma, float* __restrict__ out)
{
    extern __shared__ uint8_t smO[];    // [4][STAGEB]
    __shared__ __align__(8) uint64_t s_full[4];
    __shared__ __align__(8) uint64_t s_empty[4];

    const int combo = blockIdx.y;
    const int b = combo >> 1, br = combo & 1;
    const int n0 = blockIdx.x * 128;
    const int tid = threadIdx.x;

    if (tid == 0) {
        #pragma unroll
        for (int s = 0; s < 4; s++) {
            MBARRIER_INIT(smem_u32(&s_full[s]), 256);
            MBARRIER_INIT(smem_u32(&s_empty[s]), 256);
        }
    }
    __syncthreads();

    const uint8_t* Vb = &g_v8[b][br][0][0];
    const uint8_t* Pb = &g_P8[combo][n0][0];

    // fill stage (p & 3) with K-chunk p (128 bytes per row).
    auto produce = [&](int p) {
        const int st = p & 3;
        if (p >= 4) {
            MBARRIER_WAIT_PARITY(smem_u32(&s_empty[st]), ((p >> 2) - 1) & 1);
        }
        uint8_t* base = smO + st * STAGEB;
        const int k0 = p * 128;
        #pragma unroll
        for (int s = 0; s < 8; s++) {               // V: 256 rows x 8 x 16B
            const int i = tid + s * 256;
            const int r = i >> 3, c = (i & 7) * 16;
            CP_ASYNC16(smem_u32(base + r * OPB + c),
                       Vb + (size_t)r * HWs + k0 + c);
        }
        #pragma unroll
        for (int s = 0; s < 4; s++) {               // P: 128 rows x 8 x 16B
            const int i = tid + s * 256;
            const int r = i >> 3, c = (i & 7) * 16;
            CP_ASYNC16(smem_u32(base + AHB + r * OPB + c),
                       Pb + (size_t)r * HWs + k0 + c);
        }
        CP_ASYNC_MBAR_ARRIVE_NOINC(smem_u32(&s_full[st]));
    };

    const int w = tid >> 5, l = tid & 31;
    const int wc = w >> 1, wn = w & 1;          // 4c x 2n warp grid
    const int lrow = l & 15;
    const int lcolb = (l >> 4) * 16;            // byte offset within k-step

    float acc[4][8][4];                          // 64c x 64n per warp
    #pragma unroll
    for (int i = 0; i < 4; i++)
        #pragma unroll
        for (int j = 0; j < 8; j++)
            #pragma unroll
            for (int q = 0; q < 4; q++) acc[i][j][q] = 0.0f;

    produce(0);
    produce(1);

    for (int kt = 0; kt < NKT; kt++) {
        const int st = kt & 3;
        MBARRIER_WAIT_PARITY(smem_u32(&s_full[st]), (kt >> 2) & 1);
        if (kt + 2 < NKT) produce(kt + 2);

        const uint8_t* base = smO + st * STAGEB;
        const uint32_t a_base = smem_u32(base + (wc * 64) * OPB);
        const uint32_t b_base = smem_u32(base + AHB + (wn * 64) * OPB);

        #pragma unroll
        for (int ks = 0; ks < 4; ks++) {            // 4 x k32 steps per chunk
            const int kb = ks * 32;                 // byte offset
            uint32_t af[4][4], bf[4][4];
            #pragma unroll
            for (int mi = 0; mi < 4; mi++)
                ldmatrix_x4(af[mi], a_base + (mi * 16 + lrow) * OPB + kb + lcolb);
            #pragma unroll
            for (int nj = 0; nj < 4; nj++)
                ldmatrix_x4(bf[nj], b_base + (nj * 16 + lrow) * OPB + kb + lcolb);
            #pragma unroll
            for (int mi = 0; mi < 4; mi++)
                #pragma unroll
                for (int ni = 0; ni < 8; ni++)
                    mma_fp8(acc[mi][ni], af[mi],
                            bf[ni >> 1][ni & 1], bf[ni >> 1][(ni & 1) + 2]);
        }
        MBAR_ARRIVE(smem_u32(&s_empty[st]));
    }

    const float g = gamma[0];
    const float* x = (br ? x2 : x1) + (size_t)b * Cc * HWs;
    float* ob = out + (size_t)(br * 2 + b) * Cc * HWs;

    const int cb = wc * 64 + (l >> 2);
    const int nb = n0 + wn * 64 + (l & 3) * 2;
    #pragma unroll
    for (int ni = 0; ni < 8; ni++) {
        const int n = nb + ni * 8;
        float2 rs = *reinterpret_cast<const float2*>(&g_rowsum[combo][n]);
        const float s0 = __fdividef(g, rs.x);
        const float s1 = __fdividef(g, rs.y);
        #pragma unroll
        for (int mi = 0; mi < 4; mi++) {
            const int c = cb + mi * 16;
            {
                float2 xi = *reinterpret_cast<const float2*>(x + (size_t)c * HWs + n);
                float2 o;
                o.x = fmaf(s0, acc[mi][ni][0], xi.x);
                o.y = fmaf(s1, acc[mi][ni][1], xi.y);
                *reinterpret_cast<float2*>(ob + (size_t)c * HWs + n) = o;
            }
            {
                float2 xi = *reinterpret_cast<const float2*>(x + (size_t)(c + 8) * HWs + n);
                float2 o;
                o.x = fmaf(s0, acc[mi][ni][2], xi.x);
                o.y = fmaf(s1, acc[mi][ni][3], xi.y);
                *reinterpret_cast<float2*>(ob + (size_t)(c + 8) * HWs + n) = o;
            }
        }
    }
}

// ---------------------------------------------------------------------------
extern "C" void kernel_launch(void* const* d_in, const int* in_sizes, int n_in,
                              void* d_out, int out_size)
{
    const float* input1 = (const float*)d_in[0];
    const float* input2 = (const float*)d_in[1];
    const float* Wq1 = (const float*)d_in[2];
    const float* bq1 = (const float*)d_in[3];
    const float* Wk1 = (const float*)d_in[4];
    const float* bk1 = (const float*)d_in[5];
    const float* Wv1 = (const float*)d_in[6];
    const float* bv1 = (const float*)d_in[7];
    const float* Wq2 = (const float*)d_in[8];
    const float* bq2 = (const float*)d_in[9];
    const float* Wk2 = (const float*)d_in[10];
    const float* bk2 = (const float*)d_in[11];
    const float* Wv2 = (const float*)d_in[12];
    const float* bv2 = (const float*)d_in[13];
    const float* gamma = (const float*)d_in[14];
    float* out = (float*)d_out;

    const int smP_bytes = (64 + 128) * PAP * (int)sizeof(__half);
    const int smL_bytes = (128 + 256) * LP * (int)sizeof(__half);    // 104448
    const int smO_bytes = 4 * STAGEB;                                 // 221184
    static bool attr_done = false;
    if (!attr_done) {
        cudaFuncSetAttribute(proj_mma,   cudaFuncAttributeMaxDynamicSharedMemorySize, smP_bytes);
        cudaFuncSetAttribute(logits_mma, cudaFuncAttributeMaxDynamicSharedMemorySize, smL_bytes);
        cudaFuncSetAttribute(out_mma,    cudaFuncAttributeMaxDynamicSharedMemorySize, smO_bytes);
        attr_done = true;
    }

    void* rs_addr = nullptr;
    cudaGetSymbolAddress(&rs_addr, g_rowsum);
    cudaMemsetAsync(rs_addr, 0, 4 * HWs * sizeof(float));

    xt_kernel<<<dim3(128, 8, 4), 256>>>(input1, input2);
    proj_mma<<<dim3(32, 7, 4), 256, smP_bytes>>>(
        Wq1, bq1, Wk1, bk1, Wv1, bv1,
        Wq2, bq2, Wk2, bk2, Wv2, bv2);
    logits_mma<<<dim3(16, 32, 4), 256, smL_bytes>>>();
    out_mma<<<dim3(32, 4), 256, smO_bytes>>>(input1, input2, gamma, out);
}

// round 17
// speedup vs baseline: 1.1017x; 1.0103x over previous
#include <cuda_runtime.h>
#include <cuda_fp16.h>
#include <cuda_fp8.h>
#include <cstdint>

#define HWs 4096
#define Cc  256
#define NB  2

// ---------------- scratch -------------------------------------------------------
__device__ __align__(256) __half g_xt[4][HWs][Cc];
__device__ __align__(256) __half g_q[NB][HWs][128];
__device__ __align__(256) __half g_k[NB][2][HWs][128];
__device__ __align__(256) uint8_t g_v8[NB][2][Cc][HWs];   // V in e4m3
__device__ __align__(256) uint8_t g_P8[4][HWs][HWs];      // exp(S-6) in e4m3
__device__ __align__(256) float g_rowsum[4][HWs];

// ---------------- helpers --------------------------------------------------------
__device__ __forceinline__ uint32_t smem_u32(const void* p) {
    uint32_t a;
    asm("{ .reg .u64 t; cvta.to.shared.u64 t, %1; cvt.u32.u64 %0, t; }"
        : "=r"(a) : "l"(p));
    return a;
}
__device__ __forceinline__ void ldmatrix_x4(uint32_t* r, uint32_t addr) {
    asm volatile("ldmatrix.sync.aligned.m8n8.x4.shared.b16 {%0,%1,%2,%3}, [%4];"
        : "=r"(r[0]), "=r"(r[1]), "=r"(r[2]), "=r"(r[3]) : "r"(addr));
}
__device__ __forceinline__ void mma_fp8(float* d, const uint32_t* a,
                                        uint32_t b0, uint32_t b1) {
    asm volatile(
        "mma.sync.aligned.m16n8k32.row.col.f32.e4m3.e4m3.f32 "
        "{%0,%1,%2,%3}, {%4,%5,%6,%7}, {%8,%9}, {%0,%1,%2,%3};"
        : "+f"(d[0]), "+f"(d[1]), "+f"(d[2]), "+f"(d[3])
        : "r"(a[0]), "r"(a[1]), "r"(a[2]), "r"(a[3]), "r"(b0), "r"(b1));
}
__device__ __forceinline__ void mma_f16(uint32_t* d, const uint32_t* a,
                                        uint32_t b0, uint32_t b1) {
    asm volatile(
        "mma.sync.aligned.m16n8k16.row.col.f16.f16.f16.f16 "
        "{%0,%1}, {%2,%3,%4,%5}, {%6,%7}, {%0,%1};"
        : "+r"(d[0]), "+r"(d[1])
        : "r"(a[0]), "r"(a[1]), "r"(a[2]), "r"(a[3]), "r"(b0), "r"(b1));
}
#define CP_ASYNC16(dst, src) \
    asm volatile("cp.async.cg.shared.global [%0], [%1], 16;" :: "r"(dst), "l"(src))
#define CP_COMMIT() asm volatile("cp.async.commit_group;" ::: "memory")
#define CP_WAIT0()  asm volatile("cp.async.wait_group 0;" ::: "memory")

#define MBARRIER_INIT(mb, c) \
    asm volatile("mbarrier.init.shared.b64 [%0], %1;" :: "r"((uint32_t)(mb)), "r"((uint32_t)(c)) : "memory")
#define MBAR_ARRIVE(mb) \
    asm volatile("mbarrier.arrive.shared.b64 _, [%0];" :: "r"((uint32_t)(mb)) : "memory")
// NOTE: .noinc is load-bearing — default variant nets to zero and deadlocks.
#define CP_ASYNC_MBAR_ARRIVE_NOINC(mb) \
    asm volatile("cp.async.mbarrier.arrive.noinc.shared.b64 [%0];" :: "r"((uint32_t)(mb)) : "memory")

#define MBARRIER_WAIT_PARITY(mb, ph) do { \
    uint32_t _mb = (uint32_t)(mb); uint32_t _p = (uint32_t)(ph); uint32_t _done; \
    asm volatile("{\n\t.reg .pred p;\n\t" \
        "mbarrier.try_wait.parity.acquire.cta.shared::cta.b64 p, [%1], %2;\n\t" \
        "selp.b32 %0, 1, 0, p;\n\t}" : "=r"(_done) : "r"(_mb), "r"(_p) : "memory"); \
    if (!_done) { \
        asm volatile("{\n\t.reg .pred P1;\n\t" \
            "WAIT_LOOP_%=:\n\t" \
            "mbarrier.try_wait.parity.acquire.cta.shared::cta.b64 P1, [%0], %1, 0x989680;\n\t" \
            "@P1 bra.uni WAIT_DONE_%=;\n\t" \
            "bra.uni WAIT_LOOP_%=;\n\t" \
            "WAIT_DONE_%=:\n\t}" :: "r"(_mb), "r"(_p) : "memory"); \
    } \
} while (0)

__device__ __forceinline__ uint32_t pack_h2(float a, float b) {
    __half2 h = __floats2half2_rn(a, b);
    return *reinterpret_cast<uint32_t*>(&h);
}
__device__ __forceinline__ float2 unpack_h2(uint32_t w) {
    return __half22float2(*reinterpret_cast<__half2*>(&w));
}
__device__ __forceinline__ uint16_t pack_fp8x2(float a, float b) {
    return (uint16_t)__nv_cvt_float2_to_fp8x2(make_float2(a, b),
                                              __NV_SATFINITE, __NV_E4M3);
}
__device__ __forceinline__ uint16_t h2_to_fp8x2(__half2 h) {
    __half2_raw hr = *reinterpret_cast<__half2_raw*>(&h);
    return (uint16_t)__nv_cvt_halfraw2_to_fp8x2(hr, __NV_SATFINITE, __NV_E4M3);
}

// ---------------------------------------------------------------------------
// Stage 0: transpose+convert x -> g_xt[t][n][c] fp16; also zero rowsum.
// grid (128, 8, 4)
// ---------------------------------------------------------------------------
__global__ __launch_bounds__(256) void xt_kernel(
    const float* __restrict__ x1, const float* __restrict__ x2)
{
    const int t = blockIdx.z;
    const int br = t >> 1, b = t & 1;
    const float* src = (br ? x2 : x1) + (size_t)b * Cc * HWs;

    // fold rowsum zeroing in (replaces a memset launch): 4096 floats per combo
    if (blockIdx.x == 0 && blockIdx.y == 0) {
        float4* rs = reinterpret_cast<float4*>(&g_rowsum[t][0]);
        #pragma unroll
        for (int s = 0; s < 4; s++)
            rs[threadIdx.x + s * 256] = make_float4(0.f, 0.f, 0.f, 0.f);
    }

    const int n0 = blockIdx.x * 32;
    const int c0 = blockIdx.y * 32;

    __shared__ float tile[32][33];
    const int tx = threadIdx.x & 31;
    const int ty = threadIdx.x >> 5;

    #pragma unroll
    for (int j = 0; j < 4; j++) {
        const int cl = ty * 4 + j;
        tile[cl][tx] = src[(size_t)(c0 + cl) * HWs + n0 + tx];
    }
    __syncthreads();
    #pragma unroll
    for (int j = 0; j < 4; j++) {
        const int nl = ty * 4 + j;
        g_xt[t][n0 + nl][c0 + tx] = __float2half(tile[tx][nl]);
    }
}

// ---------------------------------------------------------------------------
// Stage A: projections via fp16 mma (f16 accum).  v -> e4m3.  (unchanged)
// ---------------------------------------------------------------------------
#define PAP 264

__global__ __launch_bounds__(256) void proj_mma(
    const float* __restrict__ Wq1, const float* __restrict__ bq1,
    const float* __restrict__ Wk1, const float* __restrict__ bk1,
    const float* __restrict__ Wv1, const float* __restrict__ bv1,
    const float* __restrict__ Wq2, const float* __restrict__ bq2,
    const float* __restrict__ Wk2, const float* __restrict__ bk2,
    const float* __restrict__ Wv2, const float* __restrict__ bv2)
{
    extern __shared__ __half smP[];
    __half* As = smP;
    __half* Bs = smP + 64 * PAP;

    const int combo = blockIdx.z;
    const int b  = combo >> 1;
    const int br = combo & 1;
    const int t  = br * 2 + b;

    const float* Wq = br ? Wq2 : Wq1;
    const float* Wk = br ? Wk2 : Wk1;
    const float* Wv = br ? Wv2 : Wv1;
    const float* bq = br ? bq2 : bq1;
    const float* bk = br ? bk2 : bk1;
    const float* bv = br ? bv2 : bv1;

    const int m0 = blockIdx.y * 64;
    const int n0 = blockIdx.x * 128;

    const int cls = (blockIdx.y == 0) ? 0 : (blockIdx.y < 3 ? 1 : 2);
    const float* Wbase = (cls == 0) ? Wq : (cls == 1 ? Wk : Wv);
    const int    roff  = (cls == 0) ? 0  : (cls == 1 ? 64 : 192);

    const int tid = threadIdx.x;

    #pragma unroll
    for (int s = 0; s < 16; s++) {
        const int i = tid + s * 256;
        const int r = i >> 6;
        const int c = (i & 63) * 4;
        float4 w4 = *reinterpret_cast<const float4*>(
            Wbase + (size_t)(m0 - roff + r) * Cc + c);
        uint2 v;
        v.x = pack_h2(w4.x, w4.y);
        v.y = pack_h2(w4.z, w4.w);
        *reinterpret_cast<uint2*>(&As[r * PAP + c]) = v;
    }
    #pragma unroll
    for (int s = 0; s < 16; s++) {
        const int i = tid + s * 256;
        const int r = i >> 5;
        const int c = (i & 31) * 8;
        uint4 v = *reinterpret_cast<const uint4*>(&g_xt[t][n0 + r][c]);
        *reinterpret_cast<uint4*>(&Bs[r * PAP + c]) = v;
    }
    __syncthreads();

    const int w = tid >> 5, l = tid & 31;
    const int wm = w >> 2, wn = w & 3;
    const int lrow = l & 15, lcol = (l >> 4) * 8;
    const uint32_t a_base = smem_u32(As + (wm * 32) * PAP);
    const uint32_t b_base = smem_u32(Bs + (wn * 32) * PAP);

    uint32_t acc[2][4][2];
    #pragma unroll
    for (int i = 0; i < 2; i++)
        #pragma unroll
        for (int j = 0; j < 4; j++) { acc[i][j][0] = 0u; acc[i][j][1] = 0u; }

    #pragma unroll
    for (int k = 0; k < 256; k += 16) {
        uint32_t af[2][4], bf[2][4];
        #pragma unroll
        for (int mi = 0; mi < 2; mi++)
            ldmatrix_x4(af[mi], a_base + ((mi * 16 + lrow) * PAP + k + lcol) * 2);
        #pragma unroll
        for (int nj = 0; nj < 2; nj++)
            ldmatrix_x4(bf[nj], b_base + ((nj * 16 + lrow) * PAP + k + lcol) * 2);
        #pragma unroll
        for (int mi = 0; mi < 2; mi++)
            #pragma unroll
            for (int ni = 0; ni < 4; ni++)
                mma_f16(acc[mi][ni], af[mi], bf[ni >> 1][ni & 1], bf[ni >> 1][(ni & 1) + 2]);
    }

    #pragma unroll
    for (int mi = 0; mi < 2; mi++) {
        const int r0 = wm * 32 + mi * 16 + (l >> 2);
        #pragma unroll
        for (int ni = 0; ni < 4; ni++) {
            const int n = n0 + wn * 32 + ni * 8 + (l & 3) * 2;
            float2 dlo = unpack_h2(acc[mi][ni][0]);
            float2 dhi = unpack_h2(acc[mi][ni][1]);
            if (cls == 0) {
                const int r = m0 + r0, r8 = r + 8;
                g_q[b][n][2 * r + br]      = __float2half(dlo.x + bq[r]);
                g_q[b][n + 1][2 * r + br]  = __float2half(dlo.y + bq[r]);
                g_q[b][n][2 * r8 + br]     = __float2half(dhi.x + bq[r8]);
                g_q[b][n + 1][2 * r8 + br] = __float2half(dhi.y + bq[r8]);
            } else if (cls == 1) {
                const int c = m0 - 64 + r0, c8 = c + 8;
                g_k[b][br][n][c]      = __float2half(dlo.x + bk[c]);
                g_k[b][br][n + 1][c]  = __float2half(dlo.y + bk[c]);
                g_k[b][br][n][c8]     = __float2half(dhi.x + bk[c8]);
                g_k[b][br][n + 1][c8] = __float2half(dhi.y + bk[c8]);
            } else {
                const int c = m0 - 192 + r0, c8 = c + 8;
                *reinterpret_cast<uint16_t*>(&g_v8[b][br][c][n]) =
                    pack_fp8x2(dlo.x + bv[c], dlo.y + bv[c]);
                *reinterpret_cast<uint16_t*>(&g_v8[b][br][c8][n]) =
                    pack_fp8x2(dhi.x + bv[c8], dhi.y + bv[c8]);
            }
        }
    }
}

// ---------------------------------------------------------------------------
// Stage B: logits (f16 accum) -> exp(S-6) e4m3 + row sums.
// cp.async tile loads.  Block tile 128n x 256m; 8 warps (2n x 4m).
// grid (16 m, 32 n, 4 combos)
// ---------------------------------------------------------------------------
#define LP  136
#define LSP 264

__global__ __launch_bounds__(256) void logits_mma()
{
    extern __shared__ __half smL[];
    __half* As = smL;                 // q: [128][LP]
    __half* Bs = smL + 128 * LP;      // k: [256][LP]

    const int combo = blockIdx.z;
    const int b = combo >> 1, br = combo & 1;
    const int n0 = blockIdx.y * 128;
    const int m0 = blockIdx.x * 256;
    const int tid = threadIdx.x;

    #pragma unroll
    for (int s = 0; s < 8; s++) {                 // q: 2048 x 16B via cp.async
        const int i = tid + s * 256;
        const int r = i >> 4, c = i & 15;
        CP_ASYNC16(smem_u32(&As[r * LP + c * 8]),
                   &g_q[b][n0 + r][c * 8]);
    }
    #pragma unroll
    for (int s = 0; s < 16; s++) {                // k: 4096 x 16B via cp.async
        const int i = tid + s * 256;
        const int r = i >> 4, c = i & 15;
        CP_ASYNC16(smem_u32(&Bs[r * LP + c * 8]),
                   &g_k[b][br][m0 + r][c * 8]);
    }
    CP_COMMIT();
    CP_WAIT0();
    __syncthreads();

    const int w = tid >> 5, l = tid & 31;
    const int wn = w >> 2, wm = w & 3;
    const uint32_t a_base = smem_u32(As + (wn * 64) * LP);
    const uint32_t b_base = smem_u32(Bs + (wm * 64) * LP);
    const int lrow = l & 15, lcol = (l >> 4) * 8;

    uint32_t acc[4][8][2];
    #pragma unroll
    for (int i = 0; i < 4; i++)
        #pragma unroll
        for (int j = 0; j < 8; j++) { acc[i][j][0] = 0u; acc[i][j][1] = 0u; }

    #pragma unroll
    for (int k = 0; k < 128; k += 16) {
        uint32_t af[4][4], bf[4][4];
        #pragma unroll
        for (int mi = 0; mi < 4; mi++)
            ldmatrix_x4(af[mi], a_base + ((mi * 16 + lrow) * LP + k + lcol) * 2);
        #pragma unroll
        for (int nj = 0; nj < 4; nj++)
            ldmatrix_x4(bf[nj], b_base + ((nj * 16 + lrow) * LP + k + lcol) * 2);
        #pragma unroll
        for (int mi = 0; mi < 4; mi++)
            #pragma unroll
            for (int ni = 0; ni < 8; ni++)
                mma_f16(acc[mi][ni], af[mi], bf[ni >> 1][ni & 1], bf[ni >> 1][(ni & 1) + 2]);
    }

    __syncthreads();
    __half* St = As;
    const int nbl = wn * 64 + (l >> 2);
    const int mbl = wm * 64 + (l & 3) * 2;
    #pragma unroll
    for (int mi = 0; mi < 4; mi++) {
        #pragma unroll
        for (int ni = 0; ni < 8; ni++) {
            float2 dlo = unpack_h2(acc[mi][ni][0]);
            float2 dhi = unpack_h2(acc[mi][ni][1]);
            *reinterpret_cast<uint32_t*>(&St[(nbl + mi * 16) * LSP + mbl + ni * 8]) =
                pack_h2(__expf(dlo.x - 6.0f), __expf(dlo.y - 6.0f));
            *reinterpret_cast<uint32_t*>(&St[(nbl + mi * 16 + 8) * LSP + mbl + ni * 8]) =
                pack_h2(__expf(dhi.x - 6.0f), __expf(dhi.y - 6.0f));
        }
    }
    __syncthreads();

    #pragma unroll
    for (int s = 0; s < 16; s++) {
        const int i = tid + s * 256;
        const int r = i >> 5, c = (i & 31) * 8;
        uint4 v = *reinterpret_cast<const uint4*>(&St[r * LSP + c]);
        const __half2* hp = reinterpret_cast<const __half2*>(&v);
        uint2 o;
        o.x = (uint32_t)h2_to_fp8x2(hp[0]) | ((uint32_t)h2_to_fp8x2(hp[1]) << 16);
        o.y = (uint32_t)h2_to_fp8x2(hp[2]) | ((uint32_t)h2_to_fp8x2(hp[3]) << 16);
        *reinterpret_cast<uint2*>(&g_P8[combo][n0 + r][m0 + c]) = o;
    }

    {
        const int r = tid >> 1;
        const int half = tid & 1;
        const uint32_t* row = reinterpret_cast<const uint32_t*>(&St[r * LSP + half * 128]);
        float s = 0.0f;
        #pragma unroll
        for (int j = 0; j < 64; j++) {
            float2 p = unpack_h2(row[j]);
            s += p.x + p.y;
        }
        s += __shfl_xor_sync(0xffffffffu, s, 1);
        if (half == 0) atomicAdd(&g_rowsum[combo][n0 + r], s);
    }
}

// ---------------------------------------------------------------------------
// Stage D: FP8 QMMA out GEMM.  (unchanged from R15)
// 4-stage mbarrier ring, 8 warps 64c x 64n, K-chunk 128B.
// grid (32 n, 4 combos) = 128 blocks = 1 wave.
// ---------------------------------------------------------------------------
#define OPB    144
#define AHB    (256 * OPB)
#define STAGEB (384 * OPB)
#define NKT    32

__global__ __launch_bounds__(256, 1) void out_mma(
    const float* __restrict__ x1, const float* __restrict__ x2,
    const float* __restrict__ gamma, float* __restrict__ out)
{
    extern __shared__ uint8_t smO[];
    __shared__ __align__(8) uint64_t s_full[4];
    __shared__ __align__(8) uint64_t s_empty[4];

    const int combo = blockIdx.y;
    const int b = combo >> 1, br = combo & 1;
    const int n0 = blockIdx.x * 128;
    const int tid = threadIdx.x;

    if (tid == 0) {
        #pragma unroll
        for (int s = 0; s < 4; s++) {
            MBARRIER_INIT(smem_u32(&s_full[s]), 256);
            MBARRIER_INIT(smem_u32(&s_empty[s]), 256);
        }
    }
    __syncthreads();

    const uint8_t* Vb = &g_v8[b][br][0][0];
    const uint8_t* Pb = &g_P8[combo][n0][0];

    auto produce = [&](int p) {
        const int st = p & 3;
        if (p >= 4) {
            MBARRIER_WAIT_PARITY(smem_u32(&s_empty[st]), ((p >> 2) - 1) & 1);
        }
        uint8_t* base = smO + st * STAGEB;
        const int k0 = p * 128;
        #pragma unroll
        for (int s = 0; s < 8; s++) {
            const int i = tid + s * 256;
            const int r = i >> 3, c = (i & 7) * 16;
            CP_ASYNC16(smem_u32(base + r * OPB + c),
                       Vb + (size_t)r * HWs + k0 + c);
        }
        #pragma unroll
        for (int s = 0; s < 4; s++) {
            const int i = tid + s * 256;
            const int r = i >> 3, c = (i & 7) * 16;
            CP_ASYNC16(smem_u32(base + AHB + r * OPB + c),
                       Pb + (size_t)r * HWs + k0 + c);
        }
        CP_ASYNC_MBAR_ARRIVE_NOINC(smem_u32(&s_full[st]));
    };

    const int w = tid >> 5, l = tid & 31;
    const int wc = w >> 1, wn = w & 1;
    const int lrow = l & 15;
    const int lcolb = (l >> 4) * 16;

    float acc[4][8][4];
    #pragma unroll
    for (int i = 0; i < 4; i++)
        #pragma unroll
        for (int j = 0; j < 8; j++)
            #pragma unroll
            for (int q = 0; q < 4; q++) acc[i][j][q] = 0.0f;

    produce(0);
    produce(1);

    for (int kt = 0; kt < NKT; kt++) {
        const int st = kt & 3;
        MBARRIER_WAIT_PARITY(smem_u32(&s_full[st]), (kt >> 2) & 1);
        if (kt + 2 < NKT) produce(kt + 2);

        const uint8_t* base = smO + st * STAGEB;
        const uint32_t a_base = smem_u32(base + (wc * 64) * OPB);
        const uint32_t b_base = smem_u32(base + AHB + (wn * 64) * OPB);

        #pragma unroll
        for (int ks = 0; ks < 4; ks++) {
            const int kb = ks * 32;
            uint32_t af[4][4], bf[4][4];
            #pragma unroll
            for (int mi = 0; mi < 4; mi++)
                ldmatrix_x4(af[mi], a_base + (mi * 16 + lrow) * OPB + kb + lcolb);
            #pragma unroll
            for (int nj = 0; nj < 4; nj++)
                ldmatrix_x4(bf[nj], b_base + (nj * 16 + lrow) * OPB + kb + lcolb);
            #pragma unroll
            for (int mi = 0; mi < 4; mi++)
                #pragma unroll
                for (int ni = 0; ni < 8; ni++)
                    mma_fp8(acc[mi][ni], af[mi],
                            bf[ni >> 1][ni & 1], bf[ni >> 1][(ni & 1) + 2]);
        }
        MBAR_ARRIVE(smem_u32(&s_empty[st]));
    }

    const float g = gamma[0];
    const float* x = (br ? x2 : x1) + (size_t)b * Cc * HWs;
    float* ob = out + (size_t)(br * 2 + b) * Cc * HWs;

    const int cb = wc * 64 + (l >> 2);
    const int nb = n0 + wn * 64 + (l & 3) * 2;
    #pragma unroll
    for (int ni = 0; ni < 8; ni++) {
        const int n = nb + ni * 8;
        float2 rs = *reinterpret_cast<const float2*>(&g_rowsum[combo][n]);
        const float s0 = __fdividef(g, rs.x);
        const float s1 = __fdividef(g, rs.y);
        #pragma unroll
        for (int mi = 0; mi < 4; mi++) {
            const int c = cb + mi * 16;
            {
                float2 xi = *reinterpret_cast<const float2*>(x + (size_t)c * HWs + n);
                float2 o;
                o.x = fmaf(s0, acc[mi][ni][0], xi.x);
                o.y = fmaf(s1, acc[mi][ni][1], xi.y);
                *reinterpret_cast<float2*>(ob + (size_t)c * HWs + n) = o;
            }
            {
                float2 xi = *reinterpret_cast<const float2*>(x + (size_t)(c + 8) * HWs + n);
                float2 o;
                o.x = fmaf(s0, acc[mi][ni][2], xi.x);
                o.y = fmaf(s1, acc[mi][ni][3], xi.y);
                *reinterpret_cast<float2*>(ob + (size_t)(c + 8) * HWs + n) = o;
            }
        }
    }
}

// ---------------------------------------------------------------------------
extern "C" void kernel_launch(void* const* d_in, const int* in_sizes, int n_in,
                              void* d_out, int out_size)
{
    const float* input1 = (const float*)d_in[0];
    const float* input2 = (const float*)d_in[1];
    const float* Wq1 = (const float*)d_in[2];
    const float* bq1 = (const float*)d_in[3];
    const float* Wk1 = (const float*)d_in[4];
    const float* bk1 = (const float*)d_in[5];
    const float* Wv1 = (const float*)d_in[6];
    const float* bv1 = (const float*)d_in[7];
    const float* Wq2 = (const float*)d_in[8];
    const float* bq2 = (const float*)d_in[9];
    const float* Wk2 = (const float*)d_in[10];
    const float* bk2 = (const float*)d_in[11];
    const float* Wv2 = (const float*)d_in[12];
    const float* bv2 = (const float*)d_in[13];
    const float* gamma = (const float*)d_in[14];
    float* out = (float*)d_out;

    const int smP_bytes = (64 + 128) * PAP * (int)sizeof(__half);
    const int smL_bytes = (128 + 256) * LP * (int)sizeof(__half);    // 104448
    const int smO_bytes = 4 * STAGEB;                                 // 221184
    static bool attr_done = false;
    if (!attr_done) {
        cudaFuncSetAttribute(proj_mma,   cudaFuncAttributeMaxDynamicSharedMemorySize, smP_bytes);
        cudaFuncSetAttribute(logits_mma, cudaFuncAttributeMaxDynamicSharedMemorySize, smL_bytes);
        cudaFuncSetAttribute(out_mma,    cudaFuncAttributeMaxDynamicSharedMemorySize, smO_bytes);
        attr_done = true;
    }

    xt_kernel<<<dim3(128, 8, 4), 256>>>(input1, input2);
    proj_mma<<<dim3(32, 7, 4), 256, smP_bytes>>>(
        Wq1, bq1, Wk1, bk1, Wv1, bv1,
        Wq2, bq2, Wk2, bk2, Wv2, bv2);
    logits_mma<<<dim3(16, 32, 4), 256, smL_bytes>>>();
    out_mma<<<dim3(32, 4), 256, smO_bytes>>>(input1, input2, gamma, out);
}